// round 1
// baseline (speedup 1.0000x reference)
#include <cuda_runtime.h>
#include <math_constants.h>
#include <cstdint>

#define Nn 50000
#define En 500000
#define IN_DIM 128
#define Hh 8
#define HD 256
#define PERMD 100
#define Bb 64
#define Cc 10
#define SLOPE 0.2f

// ---------------- scratch (static device globals; no runtime allocation) ---
__device__ float g_z[(size_t)Nn * HD];    // z of current layer (gemm output)
__device__ float g_h1[(size_t)Nn * HD];   // layer-1 output (relu'd)
__device__ float g_h2[(size_t)Nn * HD];   // layer-2 output
__device__ float g_el[Nn * Hh];
__device__ float g_er[Nn * Hh];
__device__ int   g_rowoff[Nn + 1];
__device__ int   g_cursor[Nn];
__device__ int   g_eidx[En];
__device__ int   g_gbound[Bb + 1];
__device__ float g_hg[Bb * HD];

// ---------------- CSR build ------------------------------------------------
__global__ void k_zero_counts() {
    int i = blockIdx.x * blockDim.x + threadIdx.x;
    if (i < Nn) g_cursor[i] = 0;
}

__global__ void k_count(const int* __restrict__ dstv) {
    int e = blockIdx.x * blockDim.x + threadIdx.x;
    if (e < En) atomicAdd(&g_cursor[dstv[e]], 1);
}

// single-block inclusive scan over counts -> row offsets (and cursor re-init)
__global__ void k_scan() {
    __shared__ int sh[1024];
    __shared__ int carry;
    if (threadIdx.x == 0) carry = 0;
    __syncthreads();
    for (int base = 0; base < Nn; base += 1024) {
        int i = base + threadIdx.x;
        int v = (i < Nn) ? g_cursor[i] : 0;
        sh[threadIdx.x] = v;
        __syncthreads();
        #pragma unroll
        for (int off = 1; off < 1024; off <<= 1) {
            int t = (threadIdx.x >= off) ? sh[threadIdx.x - off] : 0;
            __syncthreads();
            sh[threadIdx.x] += t;
            __syncthreads();
        }
        int excl = sh[threadIdx.x] - v;
        if (i < Nn) {
            g_rowoff[i] = carry + excl;
            g_cursor[i] = carry + excl;
        }
        __syncthreads();
        if (threadIdx.x == 0) carry += sh[1023];
        __syncthreads();
    }
    if (threadIdx.x == 0) g_rowoff[Nn] = carry;
}

__global__ void k_scatter(const int* __restrict__ dstv) {
    int e = blockIdx.x * blockDim.x + threadIdx.x;
    if (e < En) {
        int p = atomicAdd(&g_cursor[dstv[e]], 1);
        g_eidx[p] = e;
    }
}

// ---------------- SGEMM: C(g_z)[M,256] = A[M,K] @ W[K,256] -----------------
__global__ __launch_bounds__(256) void k_sgemm(const float* __restrict__ Aext,
                                               const float* __restrict__ W,
                                               int K, int a_sel) {
    const int BM = 128, BN = 128, BK = 8;
    const float* A = a_sel ? g_h1 : Aext;
    __shared__ float As[BK][BM];
    __shared__ float Bs[BK][BN];
    int tid = threadIdx.x;
    int row0 = blockIdx.y * BM;
    int col0 = blockIdx.x * BN;
    int tx = tid & 15, ty = tid >> 4;

    float acc[8][8];
    #pragma unroll
    for (int i = 0; i < 8; i++)
        #pragma unroll
        for (int j = 0; j < 8; j++) acc[i][j] = 0.f;

    int aRow = tid >> 1, aCol = (tid & 1) * 4;
    int bRow = tid >> 5, bCol = (tid & 31) * 4;

    for (int k0 = 0; k0 < K; k0 += BK) {
        float4 av;
        int gr = row0 + aRow;
        if (gr < Nn) av = *(const float4*)(A + (size_t)gr * K + k0 + aCol);
        else av = make_float4(0.f, 0.f, 0.f, 0.f);
        As[aCol + 0][aRow] = av.x;
        As[aCol + 1][aRow] = av.y;
        As[aCol + 2][aRow] = av.z;
        As[aCol + 3][aRow] = av.w;
        *(float4*)&Bs[bRow][bCol] =
            *(const float4*)(W + (size_t)(k0 + bRow) * HD + col0 + bCol);
        __syncthreads();
        #pragma unroll
        for (int kk = 0; kk < BK; kk++) {
            float4 a0 = *(const float4*)&As[kk][ty * 8];
            float4 a1 = *(const float4*)&As[kk][ty * 8 + 4];
            float4 b0 = *(const float4*)&Bs[kk][tx * 8];
            float4 b1 = *(const float4*)&Bs[kk][tx * 8 + 4];
            float a[8] = {a0.x, a0.y, a0.z, a0.w, a1.x, a1.y, a1.z, a1.w};
            float b[8] = {b0.x, b0.y, b0.z, b0.w, b1.x, b1.y, b1.z, b1.w};
            #pragma unroll
            for (int i = 0; i < 8; i++)
                #pragma unroll
                for (int j = 0; j < 8; j++) acc[i][j] = fmaf(a[i], b[j], acc[i][j]);
        }
        __syncthreads();
    }
    #pragma unroll
    for (int i = 0; i < 8; i++) {
        int r = row0 + ty * 8 + i;
        if (r < Nn) {
            float4 c0 = make_float4(acc[i][0], acc[i][1], acc[i][2], acc[i][3]);
            float4 c1 = make_float4(acc[i][4], acc[i][5], acc[i][6], acc[i][7]);
            *(float4*)&g_z[(size_t)r * HD + col0 + tx * 8] = c0;
            *(float4*)&g_z[(size_t)r * HD + col0 + tx * 8 + 4] = c1;
        }
    }
}

// ---------------- attention coefficients el/er -----------------------------
__global__ void k_coef(const float* __restrict__ al, const float* __restrict__ ar) {
    int warp = (blockIdx.x * blockDim.x + threadIdx.x) >> 5;
    int lane = threadIdx.x & 31;
    if (warp >= Nn) return;
    const float* zr = g_z + (size_t)warp * HD;
    float pl[8], pr[8];
    #pragma unroll
    for (int k = 0; k < 8; k++) {
        float zv = zr[lane + 32 * k];
        pl[k] = zv * al[k * 32 + lane];
        pr[k] = zv * ar[k * 32 + lane];
    }
    #pragma unroll
    for (int k = 0; k < 8; k++) {
        float v = pl[k], w = pr[k];
        #pragma unroll
        for (int off = 16; off; off >>= 1) {
            v += __shfl_xor_sync(0xFFFFFFFFu, v, off);
            w += __shfl_xor_sync(0xFFFFFFFFu, w, off);
        }
        if (lane == 0) {
            g_el[warp * 8 + k] = v;
            g_er[warp * 8 + k] = w;
        }
    }
}

// ---------------- warp-per-node softmax + aggregation ----------------------
__global__ void k_agg(const int* __restrict__ srcv, const float* __restrict__ bias,
                      int out_sel, int do_relu) {
    int warp = (blockIdx.x * blockDim.x + threadIdx.x) >> 5;
    if (warp >= Nn) return;
    int lane = threadIdx.x & 31;
    float* out = out_sel ? g_h1 : g_h2;
    int s0 = g_rowoff[warp], s1 = g_rowoff[warp + 1];

    float acc[8];
    #pragma unroll
    for (int k = 0; k < 8; k++) acc[k] = 0.f;

    int h = lane & 7, sub = lane >> 3;
    if (s1 > s0) {
        float er_h = g_er[warp * 8 + h];
        float mx = -CUDART_INF_F;
        for (int i = s0 + sub; i < s1; i += 4) {
            int sn = srcv[g_eidx[i]];
            float ev = g_el[sn * 8 + h] + er_h;
            ev = ev > 0.f ? ev : SLOPE * ev;
            mx = fmaxf(mx, ev);
        }
        mx = fmaxf(mx, __shfl_xor_sync(0xFFFFFFFFu, mx, 8));
        mx = fmaxf(mx, __shfl_xor_sync(0xFFFFFFFFu, mx, 16));
        float sm = 0.f;
        for (int i = s0 + sub; i < s1; i += 4) {
            int sn = srcv[g_eidx[i]];
            float ev = g_el[sn * 8 + h] + er_h;
            ev = ev > 0.f ? ev : SLOPE * ev;
            sm += __expf(ev - mx);
        }
        sm += __shfl_xor_sync(0xFFFFFFFFu, sm, 8);
        sm += __shfl_xor_sync(0xFFFFFFFFu, sm, 16);
        float inv = 1.f / sm;

        for (int i = s0; i < s1; i++) {
            int sn = srcv[g_eidx[i]];
            float aval = 0.f;
            if (lane < 8) {  // lane == head here; er_h/mx/inv are this head's
                float ev = g_el[sn * 8 + lane] + er_h;
                ev = ev > 0.f ? ev : SLOPE * ev;
                aval = __expf(ev - mx) * inv;
            }
            const float* zr = g_z + (size_t)sn * HD;
            #pragma unroll
            for (int k = 0; k < 8; k++) {
                float alpha = __shfl_sync(0xFFFFFFFFu, aval, k);
                acc[k] = fmaf(alpha, zr[lane + 32 * k], acc[k]);
            }
        }
    }
    #pragma unroll
    for (int k = 0; k < 8; k++) {
        float v = acc[k] + bias[lane + 32 * k];
        if (do_relu) v = fmaxf(v, 0.f);
        out[(size_t)warp * HD + lane + 32 * k] = v;
    }
}

// ---------------- per-graph boundaries (graph_ids is sorted) ---------------
__global__ void k_gbound(const int* __restrict__ gid) {
    int g = blockIdx.x * blockDim.x + threadIdx.x;
    if (g > Bb) return;
    int lo = 0, hi = Nn;
    while (lo < hi) {
        int mid = (lo + hi) >> 1;
        if (gid[mid] < g) lo = mid + 1;
        else hi = mid;
    }
    g_gbound[g] = lo;
}

__global__ void k_mean() {  // grid = Bb, block = HD
    int b = blockIdx.x, d = threadIdx.x;
    int s = g_gbound[b], e = g_gbound[b + 1];
    float sum = 0.f;
    for (int n = s; n < e; n++) sum += g_h2[(size_t)n * HD + d];
    float cnt = (float)(e - s);
    if (cnt < 1.f) cnt = 1.f;
    g_hg[b * HD + d] = sum / cnt;
}

__global__ void k_cls(const float* __restrict__ perm, const float* __restrict__ Wc,
                      const float* __restrict__ bc, float* __restrict__ out) {
    int t = blockIdx.x * blockDim.x + threadIdx.x;
    if (t >= Bb * Cc) return;
    int b = t / Cc, c = t % Cc;
    float s = bc[c];
    #pragma unroll 4
    for (int i = 0; i < HD; i++) s = fmaf(g_hg[b * HD + i], Wc[i * Cc + c], s);
    #pragma unroll 4
    for (int i = 0; i < PERMD; i++)
        s = fmaf(perm[b * PERMD + i], Wc[(HD + i) * Cc + c], s);
    out[t] = s;
}

// ---------------- launch ---------------------------------------------------
extern "C" void kernel_launch(void* const* d_in, const int* in_sizes, int n_in,
                              void* d_out, int out_size) {
    const float* h    = (const float*)d_in[0];
    const float* perm = (const float*)d_in[1];
    const float* W1   = (const float*)d_in[2];
    const float* al1  = (const float*)d_in[3];
    const float* ar1  = (const float*)d_in[4];
    const float* b1   = (const float*)d_in[5];
    const float* W2   = (const float*)d_in[6];
    const float* al2  = (const float*)d_in[7];
    const float* ar2  = (const float*)d_in[8];
    const float* b2   = (const float*)d_in[9];
    const float* Wc   = (const float*)d_in[10];
    const float* bc   = (const float*)d_in[11];
    const int*   src  = (const int*)d_in[12];
    const int*   dstv = (const int*)d_in[13];
    const int*   gid  = (const int*)d_in[14];
    float* out = (float*)d_out;

    // CSR by destination (shared by both layers)
    k_zero_counts<<<(Nn + 255) / 256, 256>>>();
    k_count<<<(En + 255) / 256, 256>>>(dstv);
    k_scan<<<1, 1024>>>();
    k_scatter<<<(En + 255) / 256, 256>>>(dstv);

    dim3 gemm_grid(HD / 128, (Nn + 127) / 128);
    int node_warp_blocks = (Nn * 32 + 255) / 256;

    // Layer 1
    k_sgemm<<<gemm_grid, 256>>>(h, W1, IN_DIM, 0);
    k_coef<<<node_warp_blocks, 256>>>(al1, ar1);
    k_agg<<<node_warp_blocks, 256>>>(src, b1, /*out=h1*/1, /*relu*/1);

    // Layer 2
    k_sgemm<<<gemm_grid, 256>>>(nullptr, W2, HD, 1);
    k_coef<<<node_warp_blocks, 256>>>(al2, ar2);
    k_agg<<<node_warp_blocks, 256>>>(src, b2, /*out=h2*/0, /*relu*/0);

    // Readout
    k_gbound<<<1, 128>>>(gid);
    k_mean<<<Bb, HD>>>();
    k_cls<<<(Bb * Cc + 127) / 128, 128>>>(perm, Wc, bc, out);
}

// round 2
// speedup vs baseline: 1.2402x; 1.2402x over previous
#include <cuda_runtime.h>
#include <math_constants.h>
#include <cstdint>

#define Nn 50000
#define En 500000
#define IN_DIM 128
#define Hh 8
#define HD 256
#define PERMD 100
#define Bb 64
#define Cc 10
#define SLOPE 0.2f

// ---------------- scratch (static device globals; no runtime allocation) ---
__device__ float g_z[(size_t)Nn * HD];    // z of current layer (gemm output)
__device__ float g_h1[(size_t)Nn * HD];   // layer-1 output (relu'd)
__device__ float g_h2[(size_t)Nn * HD];   // layer-2 output
__device__ float g_el[Nn * Hh];
__device__ float g_er[Nn * Hh];
__device__ int   g_rowoff[Nn + 1];
__device__ int   g_cursor[Nn];
__device__ int   g_eidx[En];
__device__ int   g_gbound[Bb + 1];
__device__ float g_hg[Bb * HD];

// ---------------- CSR build ------------------------------------------------
__global__ void k_zero_counts() {
    int i = blockIdx.x * blockDim.x + threadIdx.x;
    if (i < Nn) g_cursor[i] = 0;
}

__global__ void k_count(const int* __restrict__ dstv) {
    int e = blockIdx.x * blockDim.x + threadIdx.x;
    if (e < En) atomicAdd(&g_cursor[dstv[e]], 1);
}

// single-block scan (warp-shuffle based) over counts -> row offsets
__global__ void k_scan() {
    __shared__ int wsum[32];
    __shared__ int carry;
    int tid = threadIdx.x;
    int lane = tid & 31, wid = tid >> 5;
    if (tid == 0) carry = 0;
    __syncthreads();
    for (int base = 0; base < Nn; base += 1024) {
        int i = base + tid;
        int v = (i < Nn) ? g_cursor[i] : 0;
        // warp inclusive scan
        int incl = v;
        #pragma unroll
        for (int off = 1; off < 32; off <<= 1) {
            int t = __shfl_up_sync(0xFFFFFFFFu, incl, off);
            if (lane >= off) incl += t;
        }
        if (lane == 31) wsum[wid] = incl;
        __syncthreads();
        if (wid == 0) {
            int s = wsum[lane];
            #pragma unroll
            for (int off = 1; off < 32; off <<= 1) {
                int t = __shfl_up_sync(0xFFFFFFFFu, s, off);
                if (lane >= off) s += t;
            }
            wsum[lane] = s;
        }
        __syncthreads();
        int woff = (wid > 0) ? wsum[wid - 1] : 0;
        int excl = carry + woff + incl - v;
        if (i < Nn) {
            g_rowoff[i] = excl;
            g_cursor[i] = excl;
        }
        int total = wsum[31];
        __syncthreads();
        if (tid == 0) carry += total;
        __syncthreads();
    }
    if (tid == 0) g_rowoff[Nn] = carry;
}

__global__ void k_scatter(const int* __restrict__ dstv) {
    int e = blockIdx.x * blockDim.x + threadIdx.x;
    if (e < En) {
        int p = atomicAdd(&g_cursor[dstv[e]], 1);
        g_eidx[p] = e;
    }
}

// ---------------- 3xTF32 tensor-core GEMM: g_z[M,256] = A[M,K] @ W[K,256] --
__device__ __forceinline__ void split_tf32(float x, uint32_t& hi, uint32_t& lo) {
    uint32_t h;
    asm("cvt.rna.tf32.f32 %0, %1;" : "=r"(h) : "f"(x));
    float lf = x - __uint_as_float(h);
    uint32_t l;
    asm("cvt.rna.tf32.f32 %0, %1;" : "=r"(l) : "f"(lf));
    hi = h; lo = l;
}

__device__ __forceinline__ void mma_tf32(float* c, const uint32_t* a,
                                         uint32_t b0, uint32_t b1) {
    asm volatile(
        "mma.sync.aligned.m16n8k8.row.col.f32.tf32.tf32.f32 "
        "{%0,%1,%2,%3}, {%4,%5,%6,%7}, {%8,%9}, {%0,%1,%2,%3};"
        : "+f"(c[0]), "+f"(c[1]), "+f"(c[2]), "+f"(c[3])
        : "r"(a[0]), "r"(a[1]), "r"(a[2]), "r"(a[3]), "r"(b0), "r"(b1));
}

__global__ __launch_bounds__(256) void k_gemm_tf32(const float* __restrict__ Aext,
                                                   const float* __restrict__ W,
                                                   int K, int a_sel) {
    const float* A = a_sel ? g_h1 : Aext;
    __shared__ float As[128][36];   // [m][k], pad -> frag banks 4m+k (CF)
    __shared__ float Bs[32][136];   // [k][n], pad -> frag banks 8k+n (CF)
    int tid = threadIdx.x;
    int lane = tid & 31, wid = tid >> 5;
    int wm = wid & 3, wn = wid >> 2;          // 4 warps along M, 2 along N
    int row0 = blockIdx.y * 128, col0 = blockIdx.x * 128;
    int lr = lane >> 2, lc = lane & 3;

    float acc[2][8][4];
    #pragma unroll
    for (int mt = 0; mt < 2; mt++)
        #pragma unroll
        for (int nt = 0; nt < 8; nt++)
            #pragma unroll
            for (int j = 0; j < 4; j++) acc[mt][nt][j] = 0.f;

    for (int k0 = 0; k0 < K; k0 += 32) {
        #pragma unroll
        for (int r = 0; r < 4; r++) {
            int idx = r * 256 + tid;
            int row = idx >> 3, c4 = (idx & 7) * 4;
            int gr = row0 + row;
            float4 v = make_float4(0.f, 0.f, 0.f, 0.f);
            if (gr < Nn) v = *(const float4*)(A + (size_t)gr * K + k0 + c4);
            *(float4*)&As[row][c4] = v;
        }
        #pragma unroll
        for (int r = 0; r < 4; r++) {
            int idx = r * 256 + tid;
            int kr = idx >> 5, c4 = (idx & 31) * 4;
            *(float4*)&Bs[kr][c4] =
                *(const float4*)(W + (size_t)(k0 + kr) * HD + col0 + c4);
        }
        __syncthreads();
        #pragma unroll
        for (int ks = 0; ks < 4; ks++) {
            int kk = ks * 8;
            uint32_t ahi[2][4], alo[2][4];
            #pragma unroll
            for (int mt = 0; mt < 2; mt++) {
                int mb = wm * 32 + mt * 16;
                split_tf32(As[mb + lr][kk + lc],         ahi[mt][0], alo[mt][0]);
                split_tf32(As[mb + lr + 8][kk + lc],     ahi[mt][1], alo[mt][1]);
                split_tf32(As[mb + lr][kk + lc + 4],     ahi[mt][2], alo[mt][2]);
                split_tf32(As[mb + lr + 8][kk + lc + 4], ahi[mt][3], alo[mt][3]);
            }
            #pragma unroll
            for (int nt = 0; nt < 8; nt++) {
                int nb = wn * 64 + nt * 8 + lr;
                uint32_t bh0, bl0, bh1, bl1;
                split_tf32(Bs[kk + lc][nb],     bh0, bl0);
                split_tf32(Bs[kk + lc + 4][nb], bh1, bl1);
                #pragma unroll
                for (int mt = 0; mt < 2; mt++) {
                    mma_tf32(acc[mt][nt], ahi[mt], bh0, bh1);  // hi*hi
                    mma_tf32(acc[mt][nt], alo[mt], bh0, bh1);  // lo*hi
                    mma_tf32(acc[mt][nt], ahi[mt], bl0, bl1);  // hi*lo
                }
            }
        }
        __syncthreads();
    }
    #pragma unroll
    for (int mt = 0; mt < 2; mt++) {
        #pragma unroll
        for (int nt = 0; nt < 8; nt++) {
            int r = row0 + wm * 32 + mt * 16 + lr;
            int c = col0 + wn * 64 + nt * 8 + lc * 2;
            if (r < Nn)
                *(float2*)&g_z[(size_t)r * HD + c] =
                    make_float2(acc[mt][nt][0], acc[mt][nt][1]);
            if (r + 8 < Nn)
                *(float2*)&g_z[(size_t)(r + 8) * HD + c] =
                    make_float2(acc[mt][nt][2], acc[mt][nt][3]);
        }
    }
}

// ---------------- attention coefficients el/er -----------------------------
__global__ void k_coef(const float* __restrict__ al, const float* __restrict__ ar) {
    int warp = (blockIdx.x * blockDim.x + threadIdx.x) >> 5;
    int lane = threadIdx.x & 31;
    if (warp >= Nn) return;
    const float* zr = g_z + (size_t)warp * HD;
    float pl[8], pr[8];
    #pragma unroll
    for (int k = 0; k < 8; k++) {
        float zv = zr[lane + 32 * k];
        pl[k] = zv * al[k * 32 + lane];
        pr[k] = zv * ar[k * 32 + lane];
    }
    #pragma unroll
    for (int k = 0; k < 8; k++) {
        float v = pl[k], w = pr[k];
        #pragma unroll
        for (int off = 16; off; off >>= 1) {
            v += __shfl_xor_sync(0xFFFFFFFFu, v, off);
            w += __shfl_xor_sync(0xFFFFFFFFu, w, off);
        }
        if (lane == 0) {
            g_el[warp * 8 + k] = v;
            g_er[warp * 8 + k] = w;
        }
    }
}

// ---------------- warp-per-node softmax + aggregation ----------------------
__global__ void k_agg(const int* __restrict__ srcv, const float* __restrict__ bias,
                      int out_sel, int do_relu) {
    int warp = (blockIdx.x * blockDim.x + threadIdx.x) >> 5;
    if (warp >= Nn) return;
    int lane = threadIdx.x & 31;
    float* out = out_sel ? g_h1 : g_h2;
    int s0 = g_rowoff[warp], s1 = g_rowoff[warp + 1];

    float acc[8];
    #pragma unroll
    for (int k = 0; k < 8; k++) acc[k] = 0.f;

    int h = lane & 7, sub = lane >> 3;
    if (s1 > s0) {
        float er_h = g_er[warp * 8 + h];
        float mx = -CUDART_INF_F;
        for (int i = s0 + sub; i < s1; i += 4) {
            int sn = srcv[g_eidx[i]];
            float ev = g_el[sn * 8 + h] + er_h;
            ev = ev > 0.f ? ev : SLOPE * ev;
            mx = fmaxf(mx, ev);
        }
        mx = fmaxf(mx, __shfl_xor_sync(0xFFFFFFFFu, mx, 8));
        mx = fmaxf(mx, __shfl_xor_sync(0xFFFFFFFFu, mx, 16));
        float sm = 0.f;
        for (int i = s0 + sub; i < s1; i += 4) {
            int sn = srcv[g_eidx[i]];
            float ev = g_el[sn * 8 + h] + er_h;
            ev = ev > 0.f ? ev : SLOPE * ev;
            sm += __expf(ev - mx);
        }
        sm += __shfl_xor_sync(0xFFFFFFFFu, sm, 8);
        sm += __shfl_xor_sync(0xFFFFFFFFu, sm, 16);
        float inv = 1.f / sm;

        for (int i = s0; i < s1; i++) {
            int sn = srcv[g_eidx[i]];
            float aval = 0.f;
            if (lane < 8) {
                float ev = g_el[sn * 8 + lane] + er_h;
                ev = ev > 0.f ? ev : SLOPE * ev;
                aval = __expf(ev - mx) * inv;
            }
            const float* zr = g_z + (size_t)sn * HD;
            #pragma unroll
            for (int k = 0; k < 8; k++) {
                float alpha = __shfl_sync(0xFFFFFFFFu, aval, k);
                acc[k] = fmaf(alpha, zr[lane + 32 * k], acc[k]);
            }
        }
    }
    #pragma unroll
    for (int k = 0; k < 8; k++) {
        float v = acc[k] + bias[lane + 32 * k];
        if (do_relu) v = fmaxf(v, 0.f);
        out[(size_t)warp * HD + lane + 32 * k] = v;
    }
}

// ---------------- per-graph boundaries (graph_ids is sorted) ---------------
__global__ void k_gbound(const int* __restrict__ gid) {
    int g = blockIdx.x * blockDim.x + threadIdx.x;
    if (g > Bb) return;
    int lo = 0, hi = Nn;
    while (lo < hi) {
        int mid = (lo + hi) >> 1;
        if (gid[mid] < g) lo = mid + 1;
        else hi = mid;
    }
    g_gbound[g] = lo;
}

__global__ void k_hg_zero() {
    int i = blockIdx.x * blockDim.x + threadIdx.x;
    if (i < Bb * HD) g_hg[i] = 0.f;
}

__global__ void k_mean_part() {  // grid=(Bb,8), block=HD
    int b = blockIdx.x, d = threadIdx.x;
    int s = g_gbound[b], e = g_gbound[b + 1];
    float sum = 0.f;
    for (int n = s + blockIdx.y; n < e; n += 8) sum += g_h2[(size_t)n * HD + d];
    atomicAdd(&g_hg[b * HD + d], sum);
}

__global__ void k_cls(const float* __restrict__ perm, const float* __restrict__ Wc,
                      const float* __restrict__ bc, float* __restrict__ out) {
    int t = blockIdx.x * blockDim.x + threadIdx.x;
    if (t >= Bb * Cc) return;
    int b = t / Cc, c = t % Cc;
    int cnt = g_gbound[b + 1] - g_gbound[b];
    float inv = 1.f / (float)(cnt > 0 ? cnt : 1);
    float sg = 0.f;
    #pragma unroll 4
    for (int i = 0; i < HD; i++) sg = fmaf(g_hg[b * HD + i], Wc[i * Cc + c], sg);
    float s = bc[c] + sg * inv;
    #pragma unroll 4
    for (int i = 0; i < PERMD; i++)
        s = fmaf(perm[b * PERMD + i], Wc[(HD + i) * Cc + c], s);
    out[t] = s;
}

// ---------------- launch ---------------------------------------------------
extern "C" void kernel_launch(void* const* d_in, const int* in_sizes, int n_in,
                              void* d_out, int out_size) {
    const float* h    = (const float*)d_in[0];
    const float* perm = (const float*)d_in[1];
    const float* W1   = (const float*)d_in[2];
    const float* al1  = (const float*)d_in[3];
    const float* ar1  = (const float*)d_in[4];
    const float* b1   = (const float*)d_in[5];
    const float* W2   = (const float*)d_in[6];
    const float* al2  = (const float*)d_in[7];
    const float* ar2  = (const float*)d_in[8];
    const float* b2   = (const float*)d_in[9];
    const float* Wc   = (const float*)d_in[10];
    const float* bc   = (const float*)d_in[11];
    const int*   src  = (const int*)d_in[12];
    const int*   dstv = (const int*)d_in[13];
    const int*   gid  = (const int*)d_in[14];
    float* out = (float*)d_out;

    // CSR by destination (shared by both layers)
    k_zero_counts<<<(Nn + 255) / 256, 256>>>();
    k_count<<<(En + 255) / 256, 256>>>(dstv);
    k_scan<<<1, 1024>>>();
    k_scatter<<<(En + 255) / 256, 256>>>(dstv);

    dim3 gemm_grid(HD / 128, (Nn + 127) / 128);
    int node_warp_blocks = (Nn * 32 + 255) / 256;

    // Layer 1
    k_gemm_tf32<<<gemm_grid, 256>>>(h, W1, IN_DIM, 0);
    k_coef<<<node_warp_blocks, 256>>>(al1, ar1);
    k_agg<<<node_warp_blocks, 256>>>(src, b1, /*out=h1*/1, /*relu*/1);

    // Layer 2
    k_gemm_tf32<<<gemm_grid, 256>>>(nullptr, W2, HD, 1);
    k_coef<<<node_warp_blocks, 256>>>(al2, ar2);
    k_agg<<<node_warp_blocks, 256>>>(src, b2, /*out=h2*/0, /*relu*/0);

    // Readout
    k_gbound<<<1, 128>>>(gid);
    k_hg_zero<<<(Bb * HD + 255) / 256, 256>>>();
    k_mean_part<<<dim3(Bb, 8), HD>>>();
    k_cls<<<(Bb * Cc + 127) / 128, 128>>>(perm, Wc, bc, out);
}

// round 3
// speedup vs baseline: 1.6643x; 1.3419x over previous
#include <cuda_runtime.h>
#include <cuda_bf16.h>
#include <math_constants.h>
#include <cstdint>

#define Nn 50000
#define En 500000
#define IN_DIM 128
#define Hh 8
#define HD 256
#define PERMD 100
#define Bb 64
#define Cc 10
#define SLOPE 0.2f

// ---------------- scratch (static device globals) --------------------------
__device__ __nv_bfloat16 g_zh[(size_t)Nn * HD];  // z (bf16) for edge gather
__device__ float g_h1[(size_t)Nn * HD];          // layer-1 output (relu'd)
__device__ float g_h2[(size_t)Nn * HD];          // layer-2 output
__device__ float g_el[Nn * Hh];
__device__ float g_er[Nn * Hh];
__device__ int   g_rowoff[Nn + 1];
__device__ int   g_cursor[Nn];
__device__ int   g_esrc[En];                     // src node of each CSR slot
__device__ int   g_bsum[64];
__device__ int   g_gbound[Bb + 1];
__device__ float g_hg[Bb * HD];

// ---------------- CSR build ------------------------------------------------
__global__ void k_zero_counts() {
    int i = blockIdx.x * blockDim.x + threadIdx.x;
    if (i < Nn) g_cursor[i] = 0;
}

__global__ void k_count(const int* __restrict__ dstv) {
    int e = blockIdx.x * blockDim.x + threadIdx.x;
    if (e < En) atomicAdd(&g_cursor[dstv[e]], 1);
}

// per-1024-chunk sums (49 blocks)
__global__ void k_bsum() {
    __shared__ int wsum[32];
    int t = threadIdx.x, b = blockIdx.x;
    int i = b * 1024 + t;
    int v = (i < Nn) ? g_cursor[i] : 0;
    #pragma unroll
    for (int off = 16; off; off >>= 1) v += __shfl_xor_sync(0xFFFFFFFFu, v, off);
    if ((t & 31) == 0) wsum[t >> 5] = v;
    __syncthreads();
    if (t < 32) {
        int s = wsum[t];
        #pragma unroll
        for (int off = 16; off; off >>= 1) s += __shfl_xor_sync(0xFFFFFFFFu, s, off);
        if (t == 0) g_bsum[b] = s;
    }
}

// parallel block-scan: carry from preceding block sums, local scan, write out
__global__ void k_scan2() {
    __shared__ int wsum[32];
    __shared__ int carry_s;
    int t = threadIdx.x, b = blockIdx.x;
    int lane = t & 31, wid = t >> 5;
    if (t < 32) {
        int c = (t < b) ? g_bsum[t] : 0;
        if (t + 32 < b) c += g_bsum[t + 32];
        #pragma unroll
        for (int off = 16; off; off >>= 1) c += __shfl_xor_sync(0xFFFFFFFFu, c, off);
        if (t == 0) carry_s = c;
    }
    int i = b * 1024 + t;
    int v = (i < Nn) ? g_cursor[i] : 0;
    int incl = v;
    #pragma unroll
    for (int off = 1; off < 32; off <<= 1) {
        int tv = __shfl_up_sync(0xFFFFFFFFu, incl, off);
        if (lane >= off) incl += tv;
    }
    if (lane == 31) wsum[wid] = incl;
    __syncthreads();
    if (wid == 0) {
        int s = wsum[lane];
        #pragma unroll
        for (int off = 1; off < 32; off <<= 1) {
            int tv = __shfl_up_sync(0xFFFFFFFFu, s, off);
            if (lane >= off) s += tv;
        }
        wsum[lane] = s;
    }
    __syncthreads();
    int woff = (wid > 0) ? wsum[wid - 1] : 0;
    int excl = carry_s + woff + incl - v;
    if (i < Nn) {
        g_rowoff[i] = excl;
        g_cursor[i] = excl;
    }
    if (b == 0 && t == 0) g_rowoff[Nn] = En;
}

__global__ void k_scatter(const int* __restrict__ srcv, const int* __restrict__ dstv) {
    int e = blockIdx.x * blockDim.x + threadIdx.x;
    if (e < En) {
        int p = atomicAdd(&g_cursor[dstv[e]], 1);
        g_esrc[p] = srcv[e];
    }
}

// ---------------- 3xTF32 tensor-core GEMM + fused el/er --------------------
__device__ __forceinline__ void split_tf32(float x, uint32_t& hi, uint32_t& lo) {
    uint32_t h;
    asm("cvt.rna.tf32.f32 %0, %1;" : "=r"(h) : "f"(x));
    float lf = x - __uint_as_float(h);
    uint32_t l;
    asm("cvt.rna.tf32.f32 %0, %1;" : "=r"(l) : "f"(lf));
    hi = h; lo = l;
}

__device__ __forceinline__ void mma_tf32(float* c, const uint32_t* a,
                                         uint32_t b0, uint32_t b1) {
    asm volatile(
        "mma.sync.aligned.m16n8k8.row.col.f32.tf32.tf32.f32 "
        "{%0,%1,%2,%3}, {%4,%5,%6,%7}, {%8,%9}, {%0,%1,%2,%3};"
        : "+f"(c[0]), "+f"(c[1]), "+f"(c[2]), "+f"(c[3])
        : "r"(a[0]), "r"(a[1]), "r"(a[2]), "r"(a[3]), "r"(b0), "r"(b1));
}

__global__ __launch_bounds__(256) void k_gemm_tf32(const float* __restrict__ Aext,
                                                   const float* __restrict__ W,
                                                   const float* __restrict__ al,
                                                   const float* __restrict__ ar,
                                                   int K, int a_sel) {
    const float* A = a_sel ? g_h1 : Aext;
    __shared__ float As[128][36];   // [m][k]
    __shared__ float Bs[32][136];   // [k][n]
    int tid = threadIdx.x;
    int lane = tid & 31, wid = tid >> 5;
    int wm = wid & 3, wn = wid >> 2;          // 4 warps along M, 2 along N
    int row0 = blockIdx.y * 128, col0 = blockIdx.x * 128;
    int lr = lane >> 2, lc = lane & 3;

    float acc[2][8][4];
    #pragma unroll
    for (int mt = 0; mt < 2; mt++)
        #pragma unroll
        for (int nt = 0; nt < 8; nt++)
            #pragma unroll
            for (int j = 0; j < 4; j++) acc[mt][nt][j] = 0.f;

    for (int k0 = 0; k0 < K; k0 += 32) {
        #pragma unroll
        for (int r = 0; r < 4; r++) {
            int idx = r * 256 + tid;
            int row = idx >> 3, c4 = (idx & 7) * 4;
            int gr = row0 + row;
            float4 v = make_float4(0.f, 0.f, 0.f, 0.f);
            if (gr < Nn) v = *(const float4*)(A + (size_t)gr * K + k0 + c4);
            *(float4*)&As[row][c4] = v;
        }
        #pragma unroll
        for (int r = 0; r < 4; r++) {
            int idx = r * 256 + tid;
            int kr = idx >> 5, c4 = (idx & 31) * 4;
            *(float4*)&Bs[kr][c4] =
                *(const float4*)(W + (size_t)(k0 + kr) * HD + col0 + c4);
        }
        __syncthreads();
        #pragma unroll
        for (int ks = 0; ks < 4; ks++) {
            int kk = ks * 8;
            uint32_t ahi[2][4], alo[2][4];
            #pragma unroll
            for (int mt = 0; mt < 2; mt++) {
                int mb = wm * 32 + mt * 16;
                split_tf32(As[mb + lr][kk + lc],         ahi[mt][0], alo[mt][0]);
                split_tf32(As[mb + lr + 8][kk + lc],     ahi[mt][1], alo[mt][1]);
                split_tf32(As[mb + lr][kk + lc + 4],     ahi[mt][2], alo[mt][2]);
                split_tf32(As[mb + lr + 8][kk + lc + 4], ahi[mt][3], alo[mt][3]);
            }
            #pragma unroll
            for (int nt = 0; nt < 8; nt++) {
                int nb = wn * 64 + nt * 8 + lr;
                uint32_t bh0, bl0, bh1, bl1;
                split_tf32(Bs[kk + lc][nb],     bh0, bl0);
                split_tf32(Bs[kk + lc + 4][nb], bh1, bl1);
                #pragma unroll
                for (int mt = 0; mt < 2; mt++) {
                    mma_tf32(acc[mt][nt], ahi[mt], bh0, bh1);
                    mma_tf32(acc[mt][nt], alo[mt], bh0, bh1);
                    mma_tf32(acc[mt][nt], ahi[mt], bl0, bl1);
                }
            }
        }
        __syncthreads();
    }

    // ---- store z as bf16 ----
    #pragma unroll
    for (int mt = 0; mt < 2; mt++) {
        #pragma unroll
        for (int nt = 0; nt < 8; nt++) {
            int r = row0 + wm * 32 + mt * 16 + lr;
            int c = col0 + wn * 64 + nt * 8 + lc * 2;
            if (r < Nn)
                *(__nv_bfloat162*)&g_zh[(size_t)r * HD + c] =
                    __float22bfloat162_rn(make_float2(acc[mt][nt][0], acc[mt][nt][1]));
            if (r + 8 < Nn)
                *(__nv_bfloat162*)&g_zh[(size_t)(r + 8) * HD + c] =
                    __float22bfloat162_rn(make_float2(acc[mt][nt][2], acc[mt][nt][3]));
        }
    }

    // ---- fused el/er: warp (wm,wn) covers rows wm*32..+32, 2 complete heads
    int head_base = (col0 >> 5) + wn * 2;
    float alc[2][8], arc[2][8];
    #pragma unroll
    for (int hs = 0; hs < 2; hs++)
        #pragma unroll
        for (int q = 0; q < 4; q++) {
            int d0 = q * 8 + lc * 2;
            int hg = head_base + hs;
            alc[hs][q * 2]     = al[hg * 32 + d0];
            alc[hs][q * 2 + 1] = al[hg * 32 + d0 + 1];
            arc[hs][q * 2]     = ar[hg * 32 + d0];
            arc[hs][q * 2 + 1] = ar[hg * 32 + d0 + 1];
        }
    float pel[4][2], per_[4][2];
    #pragma unroll
    for (int rs = 0; rs < 4; rs++)
        #pragma unroll
        for (int hs = 0; hs < 2; hs++) { pel[rs][hs] = 0.f; per_[rs][hs] = 0.f; }
    #pragma unroll
    for (int mt = 0; mt < 2; mt++)
        #pragma unroll
        for (int nt = 0; nt < 8; nt++) {
            int hs = nt >> 2, q = nt & 3;
            #pragma unroll
            for (int j = 0; j < 4; j++) {
                int rs = mt * 2 + (j >> 1);
                float a = acc[mt][nt][j];
                pel[rs][hs]  = fmaf(a, alc[hs][q * 2 + (j & 1)], pel[rs][hs]);
                per_[rs][hs] = fmaf(a, arc[hs][q * 2 + (j & 1)], per_[rs][hs]);
            }
        }
    #pragma unroll
    for (int rs = 0; rs < 4; rs++)
        #pragma unroll
        for (int hs = 0; hs < 2; hs++) {
            float v = pel[rs][hs], w = per_[rs][hs];
            v += __shfl_xor_sync(0xFFFFFFFFu, v, 1);
            v += __shfl_xor_sync(0xFFFFFFFFu, v, 2);
            w += __shfl_xor_sync(0xFFFFFFFFu, w, 1);
            w += __shfl_xor_sync(0xFFFFFFFFu, w, 2);
            if (lc == 0) {
                int r = row0 + wm * 32 + (rs >> 1) * 16 + (rs & 1) * 8 + lr;
                if (r < Nn) {
                    g_el[r * 8 + head_base + hs] = v;
                    g_er[r * 8 + head_base + hs] = w;
                }
            }
        }
}

// ---------------- warp-per-node online softmax + bf16 gather ---------------
__global__ void k_agg(const float* __restrict__ bias, int out_sel, int do_relu) {
    int warp = (blockIdx.x * blockDim.x + threadIdx.x) >> 5;
    if (warp >= Nn) return;
    int lane = threadIdx.x & 31;
    float* out = out_sel ? g_h1 : g_h2;
    int s0 = g_rowoff[warp], s1 = g_rowoff[warp + 1];

    float acc[8];
    #pragma unroll
    for (int k = 0; k < 8; k++) acc[k] = 0.f;

    int h = lane & 7, sub = lane >> 3;
    if (s1 > s0) {
        float er_h = g_er[warp * 8 + h];
        // online softmax stats (per subgroup, then combine)
        float mx = -CUDART_INF_F, sm = 0.f;
        for (int i = s0 + sub; i < s1; i += 4) {
            int sn = g_esrc[i];
            float ev = g_el[sn * 8 + h] + er_h;
            ev = ev > 0.f ? ev : SLOPE * ev;
            float lo = fminf(ev, mx), hi = fmaxf(ev, mx);
            float e1 = __expf(lo - hi);
            sm = (ev > mx) ? fmaf(sm, e1, 1.f) : (sm + e1);
            mx = hi;
        }
        #pragma unroll
        for (int off = 8; off <= 16; off <<= 1) {
            float om = __shfl_xor_sync(0xFFFFFFFFu, mx, off);
            float os = __shfl_xor_sync(0xFFFFFFFFu, sm, off);
            float nm = fmaxf(mx, om);
            float t1 = (mx == -CUDART_INF_F) ? 0.f : sm * __expf(mx - nm);
            float t2 = (om == -CUDART_INF_F) ? 0.f : os * __expf(om - nm);
            sm = t1 + t2;
            mx = nm;
        }
        float inv = __frcp_rn(sm);

        // gather loop: lane owns cols [lane*8, lane*8+8), head = lane>>2
        for (int base = s0; base < s1; base += 32) {
            int idx = base + lane;
            int sn_l = (idx < s1) ? g_esrc[idx] : 0;
            int cnt = min(32, s1 - base);
            for (int j = 0; j < cnt; j++) {
                int sn = __shfl_sync(0xFFFFFFFFu, sn_l, j);
                float aval = 0.f;
                if (lane < 8) {
                    float ev = g_el[sn * 8 + lane] + er_h;
                    ev = ev > 0.f ? ev : SLOPE * ev;
                    aval = __expf(ev - mx) * inv;
                }
                uint4 raw = *(const uint4*)(g_zh + (size_t)sn * HD + lane * 8);
                float alpha = __shfl_sync(0xFFFFFFFFu, aval, lane >> 2);
                float2 f0 = __bfloat1622float2(*(__nv_bfloat162*)&raw.x);
                float2 f1 = __bfloat1622float2(*(__nv_bfloat162*)&raw.y);
                float2 f2 = __bfloat1622float2(*(__nv_bfloat162*)&raw.z);
                float2 f3 = __bfloat1622float2(*(__nv_bfloat162*)&raw.w);
                acc[0] = fmaf(alpha, f0.x, acc[0]);
                acc[1] = fmaf(alpha, f0.y, acc[1]);
                acc[2] = fmaf(alpha, f1.x, acc[2]);
                acc[3] = fmaf(alpha, f1.y, acc[3]);
                acc[4] = fmaf(alpha, f2.x, acc[4]);
                acc[5] = fmaf(alpha, f2.y, acc[5]);
                acc[6] = fmaf(alpha, f3.x, acc[6]);
                acc[7] = fmaf(alpha, f3.y, acc[7]);
            }
        }
    }
    float4 o0, o1;
    float* op = out + (size_t)warp * HD + lane * 8;
    const float* bp = bias + lane * 8;
    o0.x = acc[0] + bp[0]; o0.y = acc[1] + bp[1];
    o0.z = acc[2] + bp[2]; o0.w = acc[3] + bp[3];
    o1.x = acc[4] + bp[4]; o1.y = acc[5] + bp[5];
    o1.z = acc[6] + bp[6]; o1.w = acc[7] + bp[7];
    if (do_relu) {
        o0.x = fmaxf(o0.x, 0.f); o0.y = fmaxf(o0.y, 0.f);
        o0.z = fmaxf(o0.z, 0.f); o0.w = fmaxf(o0.w, 0.f);
        o1.x = fmaxf(o1.x, 0.f); o1.y = fmaxf(o1.y, 0.f);
        o1.z = fmaxf(o1.z, 0.f); o1.w = fmaxf(o1.w, 0.f);
    }
    *(float4*)op = o0;
    *(float4*)(op + 4) = o1;
}

// ---------------- per-graph boundaries (graph_ids is sorted) ---------------
__global__ void k_gbound(const int* __restrict__ gid) {
    int g = blockIdx.x * blockDim.x + threadIdx.x;
    if (g > Bb) return;
    int lo = 0, hi = Nn;
    while (lo < hi) {
        int mid = (lo + hi) >> 1;
        if (gid[mid] < g) lo = mid + 1;
        else hi = mid;
    }
    g_gbound[g] = lo;
}

__global__ void k_hg_zero() {
    int i = blockIdx.x * blockDim.x + threadIdx.x;
    if (i < Bb * HD) g_hg[i] = 0.f;
}

__global__ void k_mean_part() {  // grid=(Bb,8), block=HD
    int b = blockIdx.x, d = threadIdx.x;
    int s = g_gbound[b], e = g_gbound[b + 1];
    float sum = 0.f;
    for (int n = s + blockIdx.y; n < e; n += 8) sum += g_h2[(size_t)n * HD + d];
    atomicAdd(&g_hg[b * HD + d], sum);
}

__global__ void k_cls(const float* __restrict__ perm, const float* __restrict__ Wc,
                      const float* __restrict__ bc, float* __restrict__ out) {
    int t = blockIdx.x * blockDim.x + threadIdx.x;
    if (t >= Bb * Cc) return;
    int b = t / Cc, c = t % Cc;
    int cnt = g_gbound[b + 1] - g_gbound[b];
    float inv = 1.f / (float)(cnt > 0 ? cnt : 1);
    float sg = 0.f;
    #pragma unroll 4
    for (int i = 0; i < HD; i++) sg = fmaf(g_hg[b * HD + i], Wc[i * Cc + c], sg);
    float s = bc[c] + sg * inv;
    #pragma unroll 4
    for (int i = 0; i < PERMD; i++)
        s = fmaf(perm[b * PERMD + i], Wc[(HD + i) * Cc + c], s);
    out[t] = s;
}

// ---------------- launch ---------------------------------------------------
extern "C" void kernel_launch(void* const* d_in, const int* in_sizes, int n_in,
                              void* d_out, int out_size) {
    const float* h    = (const float*)d_in[0];
    const float* perm = (const float*)d_in[1];
    const float* W1   = (const float*)d_in[2];
    const float* al1  = (const float*)d_in[3];
    const float* ar1  = (const float*)d_in[4];
    const float* b1   = (const float*)d_in[5];
    const float* W2   = (const float*)d_in[6];
    const float* al2  = (const float*)d_in[7];
    const float* ar2  = (const float*)d_in[8];
    const float* b2   = (const float*)d_in[9];
    const float* Wc   = (const float*)d_in[10];
    const float* bc   = (const float*)d_in[11];
    const int*   src  = (const int*)d_in[12];
    const int*   dstv = (const int*)d_in[13];
    const int*   gid  = (const int*)d_in[14];
    float* out = (float*)d_out;

    // CSR by destination (shared by both layers)
    k_zero_counts<<<(Nn + 255) / 256, 256>>>();
    k_count<<<(En + 255) / 256, 256>>>(dstv);
    k_bsum<<<49, 1024>>>();
    k_scan2<<<49, 1024>>>();
    k_scatter<<<(En + 255) / 256, 256>>>(src, dstv);

    dim3 gemm_grid(HD / 128, (Nn + 127) / 128);
    int node_warp_blocks = (Nn * 32 + 255) / 256;

    // Layer 1
    k_gemm_tf32<<<gemm_grid, 256>>>(h, W1, al1, ar1, IN_DIM, 0);
    k_agg<<<node_warp_blocks, 256>>>(b1, /*out=h1*/1, /*relu*/1);

    // Layer 2
    k_gemm_tf32<<<gemm_grid, 256>>>(nullptr, W2, al2, ar2, HD, 1);
    k_agg<<<node_warp_blocks, 256>>>(b2, /*out=h2*/0, /*relu*/0);

    // Readout
    k_gbound<<<1, 128>>>(gid);
    k_hg_zero<<<(Bb * HD + 255) / 256, 256>>>();
    k_mean_part<<<dim3(Bb, 8), HD>>>();
    k_cls<<<(Bb * Cc + 127) / 128, 128>>>(perm, Wc, bc, out);
}

// round 4
// speedup vs baseline: 2.3239x; 1.3963x over previous
#include <cuda_runtime.h>
#include <cuda_bf16.h>
#include <math_constants.h>
#include <cstdint>

#define Nn 50000
#define En 500000
#define IN_DIM 128
#define Hh 8
#define HD 256
#define PERMD 100
#define Bb 64
#define Cc 10
#define SLOPE 0.2f

// ---------------- scratch (static device globals) --------------------------
__device__ __nv_bfloat16 g_zh[(size_t)Nn * HD];  // z (bf16) for edge gather
__device__ float g_h1[(size_t)Nn * HD];          // layer-1 output (relu'd)
__device__ float g_h2[(size_t)Nn * HD];          // layer-2 output
__device__ float g_el[Nn * Hh];
__device__ float g_er[Nn * Hh];
__device__ int   g_rowoff[Nn + 1];
__device__ int   g_cursor[Nn];
__device__ int   g_esrc[En];                     // src node of each CSR slot
__device__ int   g_bsum[64];
__device__ int   g_gbound[Bb + 1];
__device__ float g_hg[Bb * HD];

// ---------------- CSR build ------------------------------------------------
__global__ void k_zero_counts() {
    int i = blockIdx.x * blockDim.x + threadIdx.x;
    if (i < Nn) g_cursor[i] = 0;
}

__global__ void k_count(const int* __restrict__ dstv) {
    int e = blockIdx.x * blockDim.x + threadIdx.x;
    if (e < En) atomicAdd(&g_cursor[dstv[e]], 1);
}

// per-1024-chunk sums (49 blocks)
__global__ void k_bsum() {
    __shared__ int wsum[32];
    int t = threadIdx.x, b = blockIdx.x;
    int i = b * 1024 + t;
    int v = (i < Nn) ? g_cursor[i] : 0;
    #pragma unroll
    for (int off = 16; off; off >>= 1) v += __shfl_xor_sync(0xFFFFFFFFu, v, off);
    if ((t & 31) == 0) wsum[t >> 5] = v;
    __syncthreads();
    if (t < 32) {
        int s = wsum[t];
        #pragma unroll
        for (int off = 16; off; off >>= 1) s += __shfl_xor_sync(0xFFFFFFFFu, s, off);
        if (t == 0) g_bsum[b] = s;
    }
}

// parallel block-scan: carry from preceding block sums, local scan, write out
__global__ void k_scan2() {
    __shared__ int wsum[32];
    __shared__ int carry_s;
    int t = threadIdx.x, b = blockIdx.x;
    int lane = t & 31, wid = t >> 5;
    if (t < 32) {
        int c = (t < b) ? g_bsum[t] : 0;
        if (t + 32 < b) c += g_bsum[t + 32];
        #pragma unroll
        for (int off = 16; off; off >>= 1) c += __shfl_xor_sync(0xFFFFFFFFu, c, off);
        if (t == 0) carry_s = c;
    }
    int i = b * 1024 + t;
    int v = (i < Nn) ? g_cursor[i] : 0;
    int incl = v;
    #pragma unroll
    for (int off = 1; off < 32; off <<= 1) {
        int tv = __shfl_up_sync(0xFFFFFFFFu, incl, off);
        if (lane >= off) incl += tv;
    }
    if (lane == 31) wsum[wid] = incl;
    __syncthreads();
    if (wid == 0) {
        int s = wsum[lane];
        #pragma unroll
        for (int off = 1; off < 32; off <<= 1) {
            int tv = __shfl_up_sync(0xFFFFFFFFu, s, off);
            if (lane >= off) s += tv;
        }
        wsum[lane] = s;
    }
    __syncthreads();
    int woff = (wid > 0) ? wsum[wid - 1] : 0;
    int excl = carry_s + woff + incl - v;
    if (i < Nn) {
        g_rowoff[i] = excl;
        g_cursor[i] = excl;
    }
    if (b == 0 && t == 0) g_rowoff[Nn] = En;
}

__global__ void k_scatter(const int* __restrict__ srcv, const int* __restrict__ dstv) {
    int e = blockIdx.x * blockDim.x + threadIdx.x;
    if (e < En) {
        int p = atomicAdd(&g_cursor[dstv[e]], 1);
        g_esrc[p] = srcv[e];
    }
}

// ---------------- single-pass TF32 tensor-core GEMM + fused el/er ----------
__device__ __forceinline__ uint32_t to_tf32(float x) {
    uint32_t r;
    asm("cvt.rna.tf32.f32 %0, %1;" : "=r"(r) : "f"(x));
    return r;
}

__device__ __forceinline__ void mma_tf32(float* c, const uint32_t* a,
                                         uint32_t b0, uint32_t b1) {
    asm volatile(
        "mma.sync.aligned.m16n8k8.row.col.f32.tf32.tf32.f32 "
        "{%0,%1,%2,%3}, {%4,%5,%6,%7}, {%8,%9}, {%0,%1,%2,%3};"
        : "+f"(c[0]), "+f"(c[1]), "+f"(c[2]), "+f"(c[3])
        : "r"(a[0]), "r"(a[1]), "r"(a[2]), "r"(a[3]), "r"(b0), "r"(b1));
}

__global__ __launch_bounds__(256) void k_gemm_tf32(const float* __restrict__ Aext,
                                                   const float* __restrict__ W,
                                                   const float* __restrict__ al,
                                                   const float* __restrict__ ar,
                                                   int K, int a_sel) {
    const float* A = a_sel ? g_h1 : Aext;
    __shared__ float As[128][36];   // [m][k]
    __shared__ float Bs[32][136];   // [k][n]
    int tid = threadIdx.x;
    int lane = tid & 31, wid = tid >> 5;
    int wm = wid & 3, wn = wid >> 2;          // 4 warps along M, 2 along N
    int row0 = blockIdx.y * 128, col0 = blockIdx.x * 128;
    int lr = lane >> 2, lc = lane & 3;

    float acc[2][8][4];
    #pragma unroll
    for (int mt = 0; mt < 2; mt++)
        #pragma unroll
        for (int nt = 0; nt < 8; nt++)
            #pragma unroll
            for (int j = 0; j < 4; j++) acc[mt][nt][j] = 0.f;

    for (int k0 = 0; k0 < K; k0 += 32) {
        #pragma unroll
        for (int r = 0; r < 4; r++) {
            int idx = r * 256 + tid;
            int row = idx >> 3, c4 = (idx & 7) * 4;
            int gr = row0 + row;
            float4 v = make_float4(0.f, 0.f, 0.f, 0.f);
            if (gr < Nn) v = *(const float4*)(A + (size_t)gr * K + k0 + c4);
            *(float4*)&As[row][c4] = v;
        }
        #pragma unroll
        for (int r = 0; r < 4; r++) {
            int idx = r * 256 + tid;
            int kr = idx >> 5, c4 = (idx & 31) * 4;
            *(float4*)&Bs[kr][c4] =
                *(const float4*)(W + (size_t)(k0 + kr) * HD + col0 + c4);
        }
        __syncthreads();
        #pragma unroll
        for (int ks = 0; ks < 4; ks++) {
            int kk = ks * 8;
            uint32_t a[2][4];
            #pragma unroll
            for (int mt = 0; mt < 2; mt++) {
                int mb = wm * 32 + mt * 16;
                a[mt][0] = to_tf32(As[mb + lr][kk + lc]);
                a[mt][1] = to_tf32(As[mb + lr + 8][kk + lc]);
                a[mt][2] = to_tf32(As[mb + lr][kk + lc + 4]);
                a[mt][3] = to_tf32(As[mb + lr + 8][kk + lc + 4]);
            }
            #pragma unroll
            for (int nt = 0; nt < 8; nt++) {
                int nb = wn * 64 + nt * 8 + lr;
                uint32_t b0 = to_tf32(Bs[kk + lc][nb]);
                uint32_t b1 = to_tf32(Bs[kk + lc + 4][nb]);
                #pragma unroll
                for (int mt = 0; mt < 2; mt++)
                    mma_tf32(acc[mt][nt], a[mt], b0, b1);
            }
        }
        __syncthreads();
    }

    // ---- store z as bf16 ----
    #pragma unroll
    for (int mt = 0; mt < 2; mt++) {
        #pragma unroll
        for (int nt = 0; nt < 8; nt++) {
            int r = row0 + wm * 32 + mt * 16 + lr;
            int c = col0 + wn * 64 + nt * 8 + lc * 2;
            if (r < Nn)
                *(__nv_bfloat162*)&g_zh[(size_t)r * HD + c] =
                    __float22bfloat162_rn(make_float2(acc[mt][nt][0], acc[mt][nt][1]));
            if (r + 8 < Nn)
                *(__nv_bfloat162*)&g_zh[(size_t)(r + 8) * HD + c] =
                    __float22bfloat162_rn(make_float2(acc[mt][nt][2], acc[mt][nt][3]));
        }
    }

    // ---- fused el/er: warp (wm,wn) covers rows wm*32..+32, 2 complete heads
    int head_base = (col0 >> 5) + wn * 2;
    float alc[2][8], arc[2][8];
    #pragma unroll
    for (int hs = 0; hs < 2; hs++)
        #pragma unroll
        for (int q = 0; q < 4; q++) {
            int d0 = q * 8 + lc * 2;
            int hg = head_base + hs;
            alc[hs][q * 2]     = al[hg * 32 + d0];
            alc[hs][q * 2 + 1] = al[hg * 32 + d0 + 1];
            arc[hs][q * 2]     = ar[hg * 32 + d0];
            arc[hs][q * 2 + 1] = ar[hg * 32 + d0 + 1];
        }
    float pel[4][2], per_[4][2];
    #pragma unroll
    for (int rs = 0; rs < 4; rs++)
        #pragma unroll
        for (int hs = 0; hs < 2; hs++) { pel[rs][hs] = 0.f; per_[rs][hs] = 0.f; }
    #pragma unroll
    for (int mt = 0; mt < 2; mt++)
        #pragma unroll
        for (int nt = 0; nt < 8; nt++) {
            int hs = nt >> 2, q = nt & 3;
            #pragma unroll
            for (int j = 0; j < 4; j++) {
                int rs = mt * 2 + (j >> 1);
                float a = acc[mt][nt][j];
                pel[rs][hs]  = fmaf(a, alc[hs][q * 2 + (j & 1)], pel[rs][hs]);
                per_[rs][hs] = fmaf(a, arc[hs][q * 2 + (j & 1)], per_[rs][hs]);
            }
        }
    #pragma unroll
    for (int rs = 0; rs < 4; rs++)
        #pragma unroll
        for (int hs = 0; hs < 2; hs++) {
            float v = pel[rs][hs], w = per_[rs][hs];
            v += __shfl_xor_sync(0xFFFFFFFFu, v, 1);
            v += __shfl_xor_sync(0xFFFFFFFFu, v, 2);
            w += __shfl_xor_sync(0xFFFFFFFFu, w, 1);
            w += __shfl_xor_sync(0xFFFFFFFFu, w, 2);
            if (lc == 0) {
                int r = row0 + wm * 32 + (rs >> 1) * 16 + (rs & 1) * 8 + lr;
                if (r < Nn) {
                    g_el[r * 8 + head_base + hs] = v;
                    g_er[r * 8 + head_base + hs] = w;
                }
            }
        }
}

// ---------------- warp-per-node online softmax + bf16 gather ---------------
__global__ void k_agg(const float* __restrict__ bias, int out_sel, int do_relu) {
    int warp = (blockIdx.x * blockDim.x + threadIdx.x) >> 5;
    if (warp >= Nn) return;
    int lane = threadIdx.x & 31;
    float* out = out_sel ? g_h1 : g_h2;
    int s0 = g_rowoff[warp], s1 = g_rowoff[warp + 1];

    float acc[8];
    #pragma unroll
    for (int k = 0; k < 8; k++) acc[k] = 0.f;

    int h = lane & 7, sub = lane >> 3;
    if (s1 > s0) {
        float er_h = g_er[warp * 8 + h];
        float mx = -CUDART_INF_F, sm = 0.f;
        for (int i = s0 + sub; i < s1; i += 4) {
            int sn = g_esrc[i];
            float ev = g_el[sn * 8 + h] + er_h;
            ev = ev > 0.f ? ev : SLOPE * ev;
            float lo = fminf(ev, mx), hi = fmaxf(ev, mx);
            float e1 = __expf(lo - hi);
            sm = (ev > mx) ? fmaf(sm, e1, 1.f) : (sm + e1);
            mx = hi;
        }
        #pragma unroll
        for (int off = 8; off <= 16; off <<= 1) {
            float om = __shfl_xor_sync(0xFFFFFFFFu, mx, off);
            float os = __shfl_xor_sync(0xFFFFFFFFu, sm, off);
            float nm = fmaxf(mx, om);
            float t1 = (mx == -CUDART_INF_F) ? 0.f : sm * __expf(mx - nm);
            float t2 = (om == -CUDART_INF_F) ? 0.f : os * __expf(om - nm);
            sm = t1 + t2;
            mx = nm;
        }
        float inv = __frcp_rn(sm);

        for (int base = s0; base < s1; base += 32) {
            int idx = base + lane;
            int sn_l = (idx < s1) ? g_esrc[idx] : 0;
            int cnt = min(32, s1 - base);
            for (int j = 0; j < cnt; j++) {
                int sn = __shfl_sync(0xFFFFFFFFu, sn_l, j);
                float aval = 0.f;
                if (lane < 8) {
                    float ev = g_el[sn * 8 + lane] + er_h;
                    ev = ev > 0.f ? ev : SLOPE * ev;
                    aval = __expf(ev - mx) * inv;
                }
                uint4 raw = *(const uint4*)(g_zh + (size_t)sn * HD + lane * 8);
                float alpha = __shfl_sync(0xFFFFFFFFu, aval, lane >> 2);
                float2 f0 = __bfloat1622float2(*(__nv_bfloat162*)&raw.x);
                float2 f1 = __bfloat1622float2(*(__nv_bfloat162*)&raw.y);
                float2 f2 = __bfloat1622float2(*(__nv_bfloat162*)&raw.z);
                float2 f3 = __bfloat1622float2(*(__nv_bfloat162*)&raw.w);
                acc[0] = fmaf(alpha, f0.x, acc[0]);
                acc[1] = fmaf(alpha, f0.y, acc[1]);
                acc[2] = fmaf(alpha, f1.x, acc[2]);
                acc[3] = fmaf(alpha, f1.y, acc[3]);
                acc[4] = fmaf(alpha, f2.x, acc[4]);
                acc[5] = fmaf(alpha, f2.y, acc[5]);
                acc[6] = fmaf(alpha, f3.x, acc[6]);
                acc[7] = fmaf(alpha, f3.y, acc[7]);
            }
        }
    }
    float4 o0, o1;
    float* op = out + (size_t)warp * HD + lane * 8;
    const float* bp = bias + lane * 8;
    o0.x = acc[0] + bp[0]; o0.y = acc[1] + bp[1];
    o0.z = acc[2] + bp[2]; o0.w = acc[3] + bp[3];
    o1.x = acc[4] + bp[4]; o1.y = acc[5] + bp[5];
    o1.z = acc[6] + bp[6]; o1.w = acc[7] + bp[7];
    if (do_relu) {
        o0.x = fmaxf(o0.x, 0.f); o0.y = fmaxf(o0.y, 0.f);
        o0.z = fmaxf(o0.z, 0.f); o0.w = fmaxf(o0.w, 0.f);
        o1.x = fmaxf(o1.x, 0.f); o1.y = fmaxf(o1.y, 0.f);
        o1.z = fmaxf(o1.z, 0.f); o1.w = fmaxf(o1.w, 0.f);
    }
    *(float4*)op = o0;
    *(float4*)(op + 4) = o1;
}

// ---------------- readout --------------------------------------------------
__global__ void k_gbound_zero(const int* __restrict__ gid) {
    // block 0 threads 0..64 compute graph boundaries; all blocks zero g_hg
    int t = blockIdx.x * blockDim.x + threadIdx.x;
    if (t < Bb * HD) g_hg[t] = 0.f;
    if (blockIdx.x == 0 && threadIdx.x <= Bb) {
        int g = threadIdx.x;
        int lo = 0, hi = Nn;
        while (lo < hi) {
            int mid = (lo + hi) >> 1;
            if (gid[mid] < g) lo = mid + 1;
            else hi = mid;
        }
        g_gbound[g] = lo;
    }
}

__global__ void k_mean_part() {  // grid=(Bb,8), block=HD
    int b = blockIdx.x, d = threadIdx.x;
    int s = g_gbound[b], e = g_gbound[b + 1];
    float sum = 0.f;
    for (int n = s + blockIdx.y; n < e; n += 8) sum += g_h2[(size_t)n * HD + d];
    atomicAdd(&g_hg[b * HD + d], sum);
}

__global__ void k_cls(const float* __restrict__ perm, const float* __restrict__ Wc,
                      const float* __restrict__ bc, float* __restrict__ out) {
    int t = blockIdx.x * blockDim.x + threadIdx.x;
    if (t >= Bb * Cc) return;
    int b = t / Cc, c = t % Cc;
    int cnt = g_gbound[b + 1] - g_gbound[b];
    float inv = 1.f / (float)(cnt > 0 ? cnt : 1);
    float sg = 0.f;
    #pragma unroll 4
    for (int i = 0; i < HD; i++) sg = fmaf(g_hg[b * HD + i], Wc[i * Cc + c], sg);
    float s = bc[c] + sg * inv;
    #pragma unroll 4
    for (int i = 0; i < PERMD; i++)
        s = fmaf(perm[b * PERMD + i], Wc[(HD + i) * Cc + c], s);
    out[t] = s;
}

// ---------------- launch ---------------------------------------------------
extern "C" void kernel_launch(void* const* d_in, const int* in_sizes, int n_in,
                              void* d_out, int out_size) {
    const float* h    = (const float*)d_in[0];
    const float* perm = (const float*)d_in[1];
    const float* W1   = (const float*)d_in[2];
    const float* al1  = (const float*)d_in[3];
    const float* ar1  = (const float*)d_in[4];
    const float* b1   = (const float*)d_in[5];
    const float* W2   = (const float*)d_in[6];
    const float* al2  = (const float*)d_in[7];
    const float* ar2  = (const float*)d_in[8];
    const float* b2   = (const float*)d_in[9];
    const float* Wc   = (const float*)d_in[10];
    const float* bc   = (const float*)d_in[11];
    const int*   src  = (const int*)d_in[12];
    const int*   dstv = (const int*)d_in[13];
    const int*   gid  = (const int*)d_in[14];
    float* out = (float*)d_out;

    // CSR by destination (shared by both layers)
    k_zero_counts<<<(Nn + 255) / 256, 256>>>();
    k_count<<<(En + 255) / 256, 256>>>(dstv);
    k_bsum<<<49, 1024>>>();
    k_scan2<<<49, 1024>>>();
    k_scatter<<<(En + 255) / 256, 256>>>(src, dstv);

    dim3 gemm_grid(HD / 128, (Nn + 127) / 128);
    int node_warp_blocks = (Nn * 32 + 255) / 256;

    // Layer 1
    k_gemm_tf32<<<gemm_grid, 256>>>(h, W1, al1, ar1, IN_DIM, 0);
    k_agg<<<node_warp_blocks, 256>>>(b1, /*out=h1*/1, /*relu*/1);

    // Layer 2
    k_gemm_tf32<<<gemm_grid, 256>>>(nullptr, W2, al2, ar2, HD, 1);
    k_agg<<<node_warp_blocks, 256>>>(b2, /*out=h2*/0, /*relu*/0);

    // Readout
    k_gbound_zero<<<(Bb * HD + 255) / 256, 256>>>(gid);
    k_mean_part<<<dim3(Bb, 8), HD>>>();
    k_cls<<<(Bb * Cc + 127) / 128, 128>>>(perm, Wc, bc, out);
}